// round 12
// baseline (speedup 1.0000x reference)
#include <cuda_runtime.h>
#include <cuda_fp16.h>
#include <cstdint>

#define NHEADS 16
#define SEQ    2048
#define EMB    1024
#define NBATCH 2
#define DHEAD  64

// Fragment-ordered gmem files (device globals; allocation-free rule).
__device__ __half g_xh[NBATCH * SEQ * EMB];    // A-frag file [mb 32][kt 16][16KB]
__device__ __half g_ctx[NBATCH * SEQ * EMB];   // A-frag file (written by attention)
__device__ __half g_wk[EMB * EMB];             // B-frag file [nb 8][kt 16][16KB]
__device__ __half g_wq[EMB * EMB];
__device__ __half g_wv[EMB * EMB];
__device__ __half g_wu[EMB * EMB];
__device__ __half g_q[NBATCH * NHEADS * SEQ * DHEAD];  // [B,H,S,D] linear
__device__ __half g_k[NBATCH * NHEADS * SEQ * DHEAD];  // per (b,h): 32 x 8KB B-frag tiles (n=seq,k=d)
__device__ __half g_v[NBATCH * NHEADS * SEQ * DHEAD];  // per (b,h): 32 x 8KB B-frag tiles (n=d,k=seq)

// ---------------------------------------------------------------------------
__device__ __forceinline__ void mma_f16(float c[4], const uint32_t a[4], const uint32_t b[2]) {
    asm volatile(
        "mma.sync.aligned.m16n8k16.row.col.f32.f16.f16.f32 "
        "{%0,%1,%2,%3}, {%4,%5,%6,%7}, {%8,%9}, {%0,%1,%2,%3};"
        : "+f"(c[0]), "+f"(c[1]), "+f"(c[2]), "+f"(c[3])
        : "r"(a[0]), "r"(a[1]), "r"(a[2]), "r"(a[3]), "r"(b[0]), "r"(b[1]));
}
__device__ __forceinline__ uint32_t pack2(float lo, float hi) {
    __half2 h = __floats2half2_rn(lo, hi);
    return *(uint32_t*)&h;
}
__device__ __forceinline__ float ex2(float x) {
    float y;
    asm("ex2.approx.f32 %0, %1;" : "=f"(y) : "f"(x));
    return y;
}
__device__ __forceinline__ uint32_t smem_u32(const void* p) {
    uint32_t a;
    asm("{ .reg .u64 t; cvta.to.shared.u64 t, %1; cvt.u32.u64 %0, t; }" : "=r"(a) : "l"(p));
    return a;
}
#define MBAR_INIT(addr, cnt) \
    asm volatile("mbarrier.init.shared.b64 [%0], %1;" :: "r"(addr), "r"(cnt) : "memory")
#define MBAR_EXPECT(addr, bytes) \
    asm volatile("mbarrier.arrive.expect_tx.shared.b64 _, [%0], %1;" :: "r"(addr), "r"(bytes) : "memory")
#define MBAR_WAIT(addr, par) do {                                              \
    uint32_t _m = (addr), _p = (par), _d;                                      \
    asm volatile("{ .reg .pred p; mbarrier.try_wait.parity.acquire.cta.shared::cta.b64 p, [%1], %2; selp.b32 %0,1,0,p; }" \
        : "=r"(_d) : "r"(_m), "r"(_p) : "memory");                             \
    while (!_d)                                                                \
        asm volatile("{ .reg .pred p; mbarrier.try_wait.parity.acquire.cta.shared::cta.b64 p, [%1], %2, 0x989680; selp.b32 %0,1,0,p; }" \
            : "=r"(_d) : "r"(_m), "r"(_p) : "memory");                         \
} while (0)
__device__ __forceinline__ void bulk_cp(uint32_t dst, const void* src, uint32_t n, uint32_t mbar) {
    asm volatile(
        "cp.async.bulk.shared::cluster.global.mbarrier::complete_tx::bytes [%0], [%1], %2, [%3];"
        :: "r"(dst), "l"(src), "r"(n), "r"(mbar) : "memory");
}

// Lane-major fragment-file byte offsets.
__device__ __forceinline__ int frag_a_off(int m, int k, int ktiles) {
    int mb = m >> 7, r = m & 127, mt = r >> 4, rr = r & 15;
    int s = (k >> 4) & 3, hf = (k & 15) >> 3, tg = (k & 7) >> 1;
    return (mb * ktiles + (k >> 6)) * 16384 + (mt * 4 + s) * 512 +
           ((rr & 7) * 4 + tg) * 16 + ((rr >> 3) + 2 * hf) * 4 + (k & 1) * 2;
}
__device__ __forceinline__ int frag_b_off(int n, int k, int ktiles) {
    int nb = n >> 7, rn = n & 127;
    int s = (k >> 4) & 3, hf = (k & 15) >> 3, tg = (k & 7) >> 1;
    return (nb * ktiles + (k >> 6)) * 16384 + ((rn >> 3) * 4 + s) * 256 +
           ((rn & 7) * 4 + tg) * 8 + hf * 4 + (k & 1) * 2;
}
__device__ __forceinline__ int tile_b_off(int n, int k) {
    int s = k >> 4, hf = (k & 15) >> 3, tg = (k & 7) >> 1;
    return ((n >> 3) * 4 + s) * 256 + ((n & 7) * 4 + tg) * 8 + hf * 4 + (k & 1) * 2;
}

// ===========================================================================
// Preround: fp32 -> fp16 + permute into fragment files.
// ===========================================================================
__global__ __launch_bounds__(256) void preround(const float4* __restrict__ x,
                                                const float4* __restrict__ wk,
                                                const float4* __restrict__ wq,
                                                const float4* __restrict__ wv,
                                                const float4* __restrict__ wu) {
    int i = blockIdx.x * 256 + threadIdx.x;
    float4 v;
    char* base;
    int o0, o1;
    if (i < 1048576) {
        v = x[i];
        int m = i >> 8, k = (i & 255) * 4;
        base = (char*)g_xh;
        o0 = frag_a_off(m, k, 16);
        o1 = frag_a_off(m, k + 2, 16);
    } else {
        int j = i - 1048576, w = j >> 18, l = j & 262143;
        const float4* src = (w == 0) ? wk : (w == 1) ? wq : (w == 2) ? wv : wu;
        base = (char*)((w == 0) ? g_wk : (w == 1) ? g_wq : (w == 2) ? g_wv : g_wu);
        v = src[l];
        int n = l >> 8, k = (l & 255) * 4;
        o0 = frag_b_off(n, k, 16);
        o1 = frag_b_off(n, k + 2, 16);
    }
    *(uint32_t*)(base + o0) = pack2(v.x, v.y);
    *(uint32_t*)(base + o1) = pack2(v.z, v.w);
}

// ===========================================================================
// fp16 NT GEMM, bulk-copy pipeline. CTA 128x128, FOUR warps (warp tile 64x64:
// crossbar bytes == tensor cycles), 16 K-iters, 3 stages x 32KB, mbarrier/stage.
// ===========================================================================
#define NKT       16
#define STG_B     32768
#define MB_OFF    (3 * STG_B)
#define GEMM_SMEM (MB_OFF + 32)

template <int MODE>
__global__ __launch_bounds__(128) void gemm_tc(const char* __restrict__ Af,
                                               const char* __restrict__ Bw0,
                                               const char* __restrict__ Bw1,
                                               const char* __restrict__ Bw2,
                                               __half* __restrict__ Cq,
                                               __half* __restrict__ Ck,
                                               __half* __restrict__ Cv,
                                               float* __restrict__ Cf,
                                               const float* __restrict__ bias) {
    extern __shared__ char sma[];
    const uint32_t smb = smem_u32(sma);
    const int tid = threadIdx.x, wid = tid >> 5, lane = tid & 31;
    const int z = blockIdx.z;
    const int wm = (wid >> 1) * 64, wn = (wid & 1) * 64;
    const char* Bf = (MODE == 1) ? Bw0 : ((z == 0) ? Bw0 : (z == 1) ? Bw1 : Bw2);
    const char* Ab = Af + (size_t)blockIdx.y * 16 * 16384;
    const char* Bb = Bf + (size_t)blockIdx.x * 16 * 16384;

    if (tid == 0) {
        MBAR_INIT(smb + MB_OFF + 0, 1);
        MBAR_INIT(smb + MB_OFF + 8, 1);
        MBAR_INIT(smb + MB_OFF + 16, 1);
    }
    __syncthreads();
#define G_ISSUE(kt) do { int _st = (kt) % 3; uint32_t _mb = smb + MB_OFF + _st * 8;      \
        MBAR_EXPECT(_mb, 32768u);                                                        \
        bulk_cp(smb + _st * STG_B,         Ab + (size_t)(kt) * 16384, 16384u, _mb);      \
        bulk_cp(smb + _st * STG_B + 16384, Bb + (size_t)(kt) * 16384, 16384u, _mb); } while (0)
    if (tid == 0) { G_ISSUE(0); G_ISSUE(1); }

    float acc[4][8][4];
#pragma unroll
    for (int i = 0; i < 4; i++)
#pragma unroll
        for (int j = 0; j < 8; j++)
#pragma unroll
            for (int q = 0; q < 4; q++) acc[i][j][q] = 0.f;

    const int mtg0 = wm >> 4, ntg0 = wn >> 3;
    for (int kt = 0; kt < NKT; kt++) {
        if (tid == 0 && kt + 2 < NKT) G_ISSUE(kt + 2);
        const int st = kt % 3;
        MBAR_WAIT(smb + MB_OFF + st * 8, (uint32_t)((kt / 3) & 1));

        const char* buf = sma + st * STG_B;
#pragma unroll
        for (int s = 0; s < 4; s++) {
            uint32_t afr[4][4], bfr[8][2];
#pragma unroll
            for (int mt = 0; mt < 4; mt++) {
                uint4 va = *(const uint4*)(buf + ((mtg0 + mt) * 4 + s) * 512 + lane * 16);
                afr[mt][0] = va.x; afr[mt][1] = va.y; afr[mt][2] = va.z; afr[mt][3] = va.w;
            }
#pragma unroll
            for (int nt = 0; nt < 8; nt++) {
                uint2 vb = *(const uint2*)(buf + 16384 + ((ntg0 + nt) * 4 + s) * 256 + lane * 8);
                bfr[nt][0] = vb.x; bfr[nt][1] = vb.y;
            }
#pragma unroll
            for (int mt = 0; mt < 4; mt++)
#pragma unroll
                for (int nt = 0; nt < 8; nt++)
                    mma_f16(acc[mt][nt], afr[mt], bfr[nt]);
        }
        __syncthreads();
    }

    const int g = lane >> 2, tg = lane & 3;
#pragma unroll
    for (int mt = 0; mt < 4; mt++)
#pragma unroll
        for (int rh = 0; rh < 2; rh++) {
            const int m = blockIdx.y * 128 + wm + mt * 16 + g + rh * 8;
#pragma unroll
            for (int nt = 0; nt < 8; nt++) {
                const int n = blockIdx.x * 128 + wn + nt * 8 + tg * 2;
                float v0 = acc[mt][nt][rh * 2], v1 = acc[mt][nt][rh * 2 + 1];
                if (MODE == 0) {
                    const int bb = m >> 11, ss = m & 2047, hh = n >> 6, dd = n & 63;
                    if (z == 0) {
                        *(__half2*)&Cq[(((size_t)bb * NHEADS + hh) * SEQ + ss) * DHEAD + dd] =
                            __floats2half2_rn(v0, v1);
                    } else if (z == 1) {
                        char* base = (char*)Ck + (((size_t)bb * NHEADS + hh) * 32 + (ss >> 6)) * 8192;
                        *(uint32_t*)(base + tile_b_off(ss & 63, dd)) = pack2(v0, v1);
                    } else {
                        char* base = (char*)Cv + (((size_t)bb * NHEADS + hh) * 32 + (ss >> 6)) * 8192;
                        *(__half*)(base + tile_b_off(dd,     ss & 63)) = __float2half_rn(v0);
                        *(__half*)(base + tile_b_off(dd + 1, ss & 63)) = __float2half_rn(v1);
                    }
                } else {
                    *(float2*)&Cf[(size_t)m * EMB + n] =
                        make_float2(v0 + bias[n], v1 + bias[n + 1]);
                }
            }
        }
}

// ===========================================================================
// fp16 causal flash attention. Q prescaled by 0.125*log2e (base-2 scores),
// exp = bare ex2.approx; l accumulated by a ones-column HMMA (oacc block 8).
// CTA 256 Q rows, 8 warps x 32 rows (MT=2). 2 stages x 16KB + 2 mbarriers.
// ===========================================================================
#define AT_MB     (2 * 16384)
#define ATTN_SMEM (AT_MB + 16)

__global__ __launch_bounds__(256) void attn_tc(const __half* __restrict__ Q,
                                               const __half* __restrict__ Kf,
                                               const __half* __restrict__ Vf,
                                               __half* __restrict__ ctx) {
    extern __shared__ char sma[];
    const uint32_t smb = smem_u32(sma);
    const int tid = threadIdx.x, wid = tid >> 5, lane = tid & 31;
    const int g = lane >> 2, tg = lane & 3;
    const int blkE = gridDim.x - 1 - blockIdx.x;
    const int h = blockIdx.y, b = blockIdx.z;
    const int wrow = blkE * 256 + wid * 32;

    const __half* qb = Q + (((size_t)b * NHEADS + h) * SEQ + wrow) * DHEAD;
    const char* kb = (const char*)Kf + ((size_t)b * NHEADS + h) * 32 * 8192;
    const char* vb = (const char*)Vf + ((size_t)b * NHEADS + h) * 32 * 8192;

    uint32_t qf[2][4][4];
    {
        const float s2e = 0.125f * 1.44269504088896f;   // 1/sqrt(D) * log2(e)
        const __half2 sc = __floats2half2_rn(s2e, s2e);
        const __half2* q2 = (const __half2*)qb;
#pragma unroll
        for (int mt = 0; mt < 2; mt++)
#pragma unroll
            for (int s = 0; s < 4; s++) {
                __half2 h0 = __hmul2(q2[(mt * 16 + g) * 32 + s * 8 + tg], sc);
                __half2 h1 = __hmul2(q2[(mt * 16 + g + 8) * 32 + s * 8 + tg], sc);
                __half2 h2 = __hmul2(q2[(mt * 16 + g) * 32 + s * 8 + tg + 4], sc);
                __half2 h3 = __hmul2(q2[(mt * 16 + g + 8) * 32 + s * 8 + tg + 4], sc);
                qf[mt][s][0] = *(uint32_t*)&h0;
                qf[mt][s][1] = *(uint32_t*)&h1;
                qf[mt][s][2] = *(uint32_t*)&h2;
                qf[mt][s][3] = *(uint32_t*)&h3;
            }
    }

    // oacc blocks 0..7 = O (d columns); block 8 = l (ones column).
    float oacc[2][9][4];
#pragma unroll
    for (int mt = 0; mt < 2; mt++)
#pragma unroll
        for (int nt = 0; nt < 9; nt++)
#pragma unroll
            for (int q = 0; q < 4; q++) oacc[mt][nt][q] = 0.f;
    float m_[2][2] = {{-1e30f, -1e30f}, {-1e30f, -1e30f}};

    if (tid == 0) {
        MBAR_INIT(smb + AT_MB + 0, 1);
        MBAR_INIT(smb + AT_MB + 8, 1);
    }
    __syncthreads();
#define A_ISSUE(jt) do { int _p = (jt) & 1; uint32_t _mb = smb + AT_MB + _p * 8;     \
        MBAR_EXPECT(_mb, 16384u);                                                    \
        bulk_cp(smb + _p * 16384,        kb + (size_t)(jt) * 8192, 8192u, _mb);      \
        bulk_cp(smb + _p * 16384 + 8192, vb + (size_t)(jt) * 8192, 8192u, _mb); } while (0)
    const int nT = 4 * blkE + 4;
    if (tid == 0) A_ISSUE(0);

    const uint32_t ONES = 0x3C003C00u;   // half2(1,1)

    for (int jt = 0; jt < nT; jt++) {
        const int p = jt & 1;
        if (tid == 0 && jt + 1 < nT) A_ISSUE(jt + 1);
        MBAR_WAIT(smb + AT_MB + p * 8, (uint32_t)((jt / 2) & 1));

        if (jt * 64 <= wrow + 31) {
            const char* Ks = sma + p * 16384;
            const char* Vs = Ks + 8192;

            float sacc[2][8][4];
#pragma unroll
            for (int mt = 0; mt < 2; mt++)
#pragma unroll
                for (int nt = 0; nt < 8; nt++)
#pragma unroll
                    for (int q = 0; q < 4; q++) sacc[mt][nt][q] = 0.f;

#pragma unroll
            for (int s = 0; s < 4; s++)
#pragma unroll
                for (int nt = 0; nt < 8; nt++) {
                    uint2 vb2 = *(const uint2*)(Ks + ((nt * 4 + s) * 256) + lane * 8);
                    uint32_t bb2[2] = {vb2.x, vb2.y};
                    mma_f16(sacc[0][nt], qf[0][s], bb2);
                    mma_f16(sacc[1][nt], qf[1][s], bb2);
                }

            if (jt * 64 + 63 > wrow) {
#pragma unroll
                for (int mt = 0; mt < 2; mt++)
#pragma unroll
                    for (int nt = 0; nt < 8; nt++) {
                        int colb = jt * 64 + nt * 8 + 2 * tg;
#pragma unroll
                        for (int rh = 0; rh < 2; rh++) {
                            int row = wrow + mt * 16 + g + 8 * rh;
                            if (colb > row)     sacc[mt][nt][rh * 2 + 0] = -1e30f;
                            if (colb + 1 > row) sacc[mt][nt][rh * 2 + 1] = -1e30f;
                        }
                    }
            }

            // online softmax (base-2): max, alpha, rescale O+l; exp deferred to PV pack
#pragma unroll
            for (int mt = 0; mt < 2; mt++) {
                float rmax[2] = {-1e30f, -1e30f};
#pragma unroll
                for (int nt = 0; nt < 8; nt++)
#pragma unroll
                    for (int rh = 0; rh < 2; rh++)
                        rmax[rh] = fmaxf(rmax[rh],
                                         fmaxf(sacc[mt][nt][rh * 2], sacc[mt][nt][rh * 2 + 1]));
#pragma unroll
                for (int rh = 0; rh < 2; rh++) {
                    rmax[rh] = fmaxf(rmax[rh], __shfl_xor_sync(0xffffffffu, rmax[rh], 1));
                    rmax[rh] = fmaxf(rmax[rh], __shfl_xor_sync(0xffffffffu, rmax[rh], 2));
                }
                float alpha[2];
#pragma unroll
                for (int rh = 0; rh < 2; rh++) {
                    float mnew = fmaxf(m_[mt][rh], rmax[rh]);
                    alpha[rh] = ex2(m_[mt][rh] - mnew);
                    m_[mt][rh] = mnew;
                }
#pragma unroll
                for (int nt = 0; nt < 9; nt++)
#pragma unroll
                    for (int rh = 0; rh < 2; rh++) {
                        oacc[mt][nt][rh * 2 + 0] *= alpha[rh];
                        oacc[mt][nt][rh * 2 + 1] *= alpha[rh];
                    }
            }

            // O += P V, l += P 1  (P = ex2(s - m) packed to fp16 on the fly)
#pragma unroll
            for (int s = 0; s < 4; s++) {
                uint32_t pa[2][4];
#pragma unroll
                for (int mt = 0; mt < 2; mt++) {
                    float m0 = m_[mt][0], m1 = m_[mt][1];
                    pa[mt][0] = pack2(ex2(sacc[mt][2 * s][0] - m0), ex2(sacc[mt][2 * s][1] - m0));
                    pa[mt][1] = pack2(ex2(sacc[mt][2 * s][2] - m1), ex2(sacc[mt][2 * s][3] - m1));
                    pa[mt][2] = pack2(ex2(sacc[mt][2 * s + 1][0] - m0), ex2(sacc[mt][2 * s + 1][1] - m0));
                    pa[mt][3] = pack2(ex2(sacc[mt][2 * s + 1][2] - m1), ex2(sacc[mt][2 * s + 1][3] - m1));
                }
#pragma unroll
                for (int ntd = 0; ntd < 8; ntd++) {
                    uint2 vb2 = *(const uint2*)(Vs + ((ntd * 4 + s) * 256) + lane * 8);
                    uint32_t bb2[2] = {vb2.x, vb2.y};
                    mma_f16(oacc[0][ntd], pa[0], bb2);
                    mma_f16(oacc[1][ntd], pa[1], bb2);
                }
                uint32_t ones2[2] = {ONES, ONES};
                mma_f16(oacc[0][8], pa[0], ones2);
                mma_f16(oacc[1][8], pa[1], ones2);
            }
        }
        __syncthreads();
    }

    // epilogue: O / l -> ctx A-frag file
#pragma unroll
    for (int mt = 0; mt < 2; mt++) {
        float inv[2] = {1.f / oacc[mt][8][0], 1.f / oacc[mt][8][2]};
#pragma unroll
        for (int rh = 0; rh < 2; rh++) {
            const int m = b * SEQ + wrow + mt * 16 + g + 8 * rh;
#pragma unroll
            for (int nt = 0; nt < 8; nt++) {
                int k = h * DHEAD + nt * 8 + 2 * tg;
                *(uint32_t*)((char*)ctx + frag_a_off(m, k, 16)) =
                    pack2(oacc[mt][nt][rh * 2] * inv[rh], oacc[mt][nt][rh * 2 + 1] * inv[rh]);
            }
        }
    }
}

// ---------------------------------------------------------------------------
extern "C" void kernel_launch(void* const* d_in, const int* in_sizes, int n_in,
                              void* d_out, int out_size) {
    const float* x  = (const float*)d_in[0];
    const float* Wk = (const float*)d_in[1];
    const float* Wq = (const float*)d_in[2];
    const float* Wv = (const float*)d_in[3];
    const float* Wu = (const float*)d_in[4];
    const float* bu = (const float*)d_in[5];
    float* out = (float*)d_out;

    __half *qp, *kp, *vp, *cp, *xh, *wk, *wq, *wv, *wu;
    cudaGetSymbolAddress((void**)&qp, g_q);
    cudaGetSymbolAddress((void**)&kp, g_k);
    cudaGetSymbolAddress((void**)&vp, g_v);
    cudaGetSymbolAddress((void**)&cp, g_ctx);
    cudaGetSymbolAddress((void**)&xh, g_xh);
    cudaGetSymbolAddress((void**)&wk, g_wk);
    cudaGetSymbolAddress((void**)&wq, g_wq);
    cudaGetSymbolAddress((void**)&wv, g_wv);
    cudaGetSymbolAddress((void**)&wu, g_wu);

    cudaFuncSetAttribute(gemm_tc<0>, cudaFuncAttributeMaxDynamicSharedMemorySize, GEMM_SMEM);
    cudaFuncSetAttribute(gemm_tc<1>, cudaFuncAttributeMaxDynamicSharedMemorySize, GEMM_SMEM);
    cudaFuncSetAttribute(attn_tc, cudaFuncAttributeMaxDynamicSharedMemorySize, ATTN_SMEM);

    preround<<<8192, 256>>>((const float4*)x, (const float4*)Wk, (const float4*)Wq,
                            (const float4*)Wv, (const float4*)Wu);

    dim3 gqkv(EMB / 128, (NBATCH * SEQ) / 128, 3);
    gemm_tc<0><<<gqkv, 128, GEMM_SMEM>>>((const char*)xh, (const char*)wq, (const char*)wk,
                                         (const char*)wv, qp, kp, vp, nullptr, nullptr);

    attn_tc<<<dim3(SEQ / 256, NHEADS, NBATCH), 256, ATTN_SMEM>>>(qp, kp, vp, cp);

    dim3 go(EMB / 128, (NBATCH * SEQ) / 128, 1);
    gemm_tc<1><<<go, 128, GEMM_SMEM>>>((const char*)cp, (const char*)wu, nullptr, nullptr,
                                       nullptr, nullptr, nullptr, out, bu);
}

// round 13
// speedup vs baseline: 1.0055x; 1.0055x over previous
#include <cuda_runtime.h>
#include <cuda_fp16.h>
#include <cstdint>

#define NHEADS 16
#define SEQ    2048
#define EMB    1024
#define NBATCH 2
#define DHEAD  64

// Fragment-ordered gmem files (device globals; allocation-free rule).
__device__ __half g_xh[NBATCH * SEQ * EMB];    // A-frag file [mb 32][kt 16][16KB]
__device__ __half g_ctx[NBATCH * SEQ * EMB];   // A-frag file (written by attention)
__device__ __half g_wk[EMB * EMB];             // B-frag file [nb 8][kt 16][16KB]
__device__ __half g_wq[EMB * EMB];
__device__ __half g_wv[EMB * EMB];
__device__ __half g_wu[EMB * EMB];
__device__ __half g_q[NBATCH * NHEADS * SEQ * DHEAD];  // [B,H,S,D] linear
__device__ __half g_k[NBATCH * NHEADS * SEQ * DHEAD];  // per (b,h): 32 x 8KB B-frag tiles (n=seq,k=d)
__device__ __half g_v[NBATCH * NHEADS * SEQ * DHEAD];  // per (b,h): 32 x 8KB B-frag tiles (n=d,k=seq)

// ---------------------------------------------------------------------------
__device__ __forceinline__ void mma_f16(float c[4], const uint32_t a[4], const uint32_t b[2]) {
    asm volatile(
        "mma.sync.aligned.m16n8k16.row.col.f32.f16.f16.f32 "
        "{%0,%1,%2,%3}, {%4,%5,%6,%7}, {%8,%9}, {%0,%1,%2,%3};"
        : "+f"(c[0]), "+f"(c[1]), "+f"(c[2]), "+f"(c[3])
        : "r"(a[0]), "r"(a[1]), "r"(a[2]), "r"(a[3]), "r"(b[0]), "r"(b[1]));
}
__device__ __forceinline__ uint32_t pack2(float lo, float hi) {
    __half2 h = __floats2half2_rn(lo, hi);
    return *(uint32_t*)&h;
}
__device__ __forceinline__ float ex2(float x) {
    float y;
    asm("ex2.approx.f32 %0, %1;" : "=f"(y) : "f"(x));
    return y;
}
__device__ __forceinline__ uint32_t smem_u32(const void* p) {
    uint32_t a;
    asm("{ .reg .u64 t; cvta.to.shared.u64 t, %1; cvt.u32.u64 %0, t; }" : "=r"(a) : "l"(p));
    return a;
}
#define MBAR_INIT(addr, cnt) \
    asm volatile("mbarrier.init.shared.b64 [%0], %1;" :: "r"(addr), "r"(cnt) : "memory")
#define MBAR_EXPECT(addr, bytes) \
    asm volatile("mbarrier.arrive.expect_tx.shared.b64 _, [%0], %1;" :: "r"(addr), "r"(bytes) : "memory")
#define MBAR_WAIT(addr, par) do {                                              \
    uint32_t _m = (addr), _p = (par), _d;                                      \
    asm volatile("{ .reg .pred p; mbarrier.try_wait.parity.acquire.cta.shared::cta.b64 p, [%1], %2; selp.b32 %0,1,0,p; }" \
        : "=r"(_d) : "r"(_m), "r"(_p) : "memory");                             \
    while (!_d)                                                                \
        asm volatile("{ .reg .pred p; mbarrier.try_wait.parity.acquire.cta.shared::cta.b64 p, [%1], %2, 0x989680; selp.b32 %0,1,0,p; }" \
            : "=r"(_d) : "r"(_m), "r"(_p) : "memory");                         \
} while (0)
__device__ __forceinline__ void bulk_cp(uint32_t dst, const void* src, uint32_t n, uint32_t mbar) {
    asm volatile(
        "cp.async.bulk.shared::cluster.global.mbarrier::complete_tx::bytes [%0], [%1], %2, [%3];"
        :: "r"(dst), "l"(src), "r"(n), "r"(mbar) : "memory");
}

// Lane-major fragment-file byte offsets.
__device__ __forceinline__ int frag_a_off(int m, int k, int ktiles) {
    int mb = m >> 7, r = m & 127, mt = r >> 4, rr = r & 15;
    int s = (k >> 4) & 3, hf = (k & 15) >> 3, tg = (k & 7) >> 1;
    return (mb * ktiles + (k >> 6)) * 16384 + (mt * 4 + s) * 512 +
           ((rr & 7) * 4 + tg) * 16 + ((rr >> 3) + 2 * hf) * 4 + (k & 1) * 2;
}
__device__ __forceinline__ int frag_b_off(int n, int k, int ktiles) {
    int nb = n >> 7, rn = n & 127;
    int s = (k >> 4) & 3, hf = (k & 15) >> 3, tg = (k & 7) >> 1;
    return (nb * ktiles + (k >> 6)) * 16384 + ((rn >> 3) * 4 + s) * 256 +
           ((rn & 7) * 4 + tg) * 8 + hf * 4 + (k & 1) * 2;
}
__device__ __forceinline__ int tile_b_off(int n, int k) {
    int s = k >> 4, hf = (k & 15) >> 3, tg = (k & 7) >> 1;
    return ((n >> 3) * 4 + s) * 256 + ((n & 7) * 4 + tg) * 8 + hf * 4 + (k & 1) * 2;
}

// ===========================================================================
// Preround: fp32 -> fp16 + permute into fragment files.
// ===========================================================================
__global__ __launch_bounds__(256) void preround(const float4* __restrict__ x,
                                                const float4* __restrict__ wk,
                                                const float4* __restrict__ wq,
                                                const float4* __restrict__ wv,
                                                const float4* __restrict__ wu) {
    int i = blockIdx.x * 256 + threadIdx.x;
    float4 v;
    char* base;
    int o0, o1;
    if (i < 1048576) {
        v = x[i];
        int m = i >> 8, k = (i & 255) * 4;
        base = (char*)g_xh;
        o0 = frag_a_off(m, k, 16);
        o1 = frag_a_off(m, k + 2, 16);
    } else {
        int j = i - 1048576, w = j >> 18, l = j & 262143;
        const float4* src = (w == 0) ? wk : (w == 1) ? wq : (w == 2) ? wv : wu;
        base = (char*)((w == 0) ? g_wk : (w == 1) ? g_wq : (w == 2) ? g_wv : g_wu);
        v = src[l];
        int n = l >> 8, k = (l & 255) * 4;
        o0 = frag_b_off(n, k, 16);
        o1 = frag_b_off(n, k + 2, 16);
    }
    *(uint32_t*)(base + o0) = pack2(v.x, v.y);
    *(uint32_t*)(base + o1) = pack2(v.z, v.w);
}

// ===========================================================================
// fp16 NT GEMM, bulk-copy pipeline. CTA 128x128, FOUR warps (warp tile 64x64:
// crossbar bytes == tensor cycles), 16 K-iters, 3 stages x 32KB, mbarrier/stage.
// ===========================================================================
#define NKT       16
#define STG_B     32768
#define MB_OFF    (3 * STG_B)
#define GEMM_SMEM (MB_OFF + 32)

template <int MODE>
__global__ __launch_bounds__(128) void gemm_tc(const char* __restrict__ Af,
                                               const char* __restrict__ Bw0,
                                               const char* __restrict__ Bw1,
                                               const char* __restrict__ Bw2,
                                               __half* __restrict__ Cq,
                                               __half* __restrict__ Ck,
                                               __half* __restrict__ Cv,
                                               float* __restrict__ Cf,
                                               const float* __restrict__ bias) {
    extern __shared__ char sma[];
    const uint32_t smb = smem_u32(sma);
    const int tid = threadIdx.x, wid = tid >> 5, lane = tid & 31;
    const int z = blockIdx.z;
    const int wm = (wid >> 1) * 64, wn = (wid & 1) * 64;
    const char* Bf = (MODE == 1) ? Bw0 : ((z == 0) ? Bw0 : (z == 1) ? Bw1 : Bw2);
    const char* Ab = Af + (size_t)blockIdx.y * 16 * 16384;
    const char* Bb = Bf + (size_t)blockIdx.x * 16 * 16384;

    if (tid == 0) {
        MBAR_INIT(smb + MB_OFF + 0, 1);
        MBAR_INIT(smb + MB_OFF + 8, 1);
        MBAR_INIT(smb + MB_OFF + 16, 1);
    }
    __syncthreads();
#define G_ISSUE(kt) do { int _st = (kt) % 3; uint32_t _mb = smb + MB_OFF + _st * 8;      \
        MBAR_EXPECT(_mb, 32768u);                                                        \
        bulk_cp(smb + _st * STG_B,         Ab + (size_t)(kt) * 16384, 16384u, _mb);      \
        bulk_cp(smb + _st * STG_B + 16384, Bb + (size_t)(kt) * 16384, 16384u, _mb); } while (0)
    if (tid == 0) { G_ISSUE(0); G_ISSUE(1); }

    float acc[4][8][4];
#pragma unroll
    for (int i = 0; i < 4; i++)
#pragma unroll
        for (int j = 0; j < 8; j++)
#pragma unroll
            for (int q = 0; q < 4; q++) acc[i][j][q] = 0.f;

    const int mtg0 = wm >> 4, ntg0 = wn >> 3;
    for (int kt = 0; kt < NKT; kt++) {
        if (tid == 0 && kt + 2 < NKT) G_ISSUE(kt + 2);
        const int st = kt % 3;
        MBAR_WAIT(smb + MB_OFF + st * 8, (uint32_t)((kt / 3) & 1));

        const char* buf = sma + st * STG_B;
#pragma unroll
        for (int s = 0; s < 4; s++) {
            uint32_t afr[4][4], bfr[8][2];
#pragma unroll
            for (int mt = 0; mt < 4; mt++) {
                uint4 va = *(const uint4*)(buf + ((mtg0 + mt) * 4 + s) * 512 + lane * 16);
                afr[mt][0] = va.x; afr[mt][1] = va.y; afr[mt][2] = va.z; afr[mt][3] = va.w;
            }
#pragma unroll
            for (int nt = 0; nt < 8; nt++) {
                uint2 vb = *(const uint2*)(buf + 16384 + ((ntg0 + nt) * 4 + s) * 256 + lane * 8);
                bfr[nt][0] = vb.x; bfr[nt][1] = vb.y;
            }
#pragma unroll
            for (int mt = 0; mt < 4; mt++)
#pragma unroll
                for (int nt = 0; nt < 8; nt++)
                    mma_f16(acc[mt][nt], afr[mt], bfr[nt]);
        }
        __syncthreads();
    }

    const int g = lane >> 2, tg = lane & 3;
#pragma unroll
    for (int mt = 0; mt < 4; mt++)
#pragma unroll
        for (int rh = 0; rh < 2; rh++) {
            const int m = blockIdx.y * 128 + wm + mt * 16 + g + rh * 8;
#pragma unroll
            for (int nt = 0; nt < 8; nt++) {
                const int n = blockIdx.x * 128 + wn + nt * 8 + tg * 2;
                float v0 = acc[mt][nt][rh * 2], v1 = acc[mt][nt][rh * 2 + 1];
                if (MODE == 0) {
                    const int bb = m >> 11, ss = m & 2047, hh = n >> 6, dd = n & 63;
                    if (z == 0) {
                        *(__half2*)&Cq[(((size_t)bb * NHEADS + hh) * SEQ + ss) * DHEAD + dd] =
                            __floats2half2_rn(v0, v1);
                    } else if (z == 1) {
                        char* base = (char*)Ck + (((size_t)bb * NHEADS + hh) * 32 + (ss >> 6)) * 8192;
                        *(uint32_t*)(base + tile_b_off(ss & 63, dd)) = pack2(v0, v1);
                    } else {
                        char* base = (char*)Cv + (((size_t)bb * NHEADS + hh) * 32 + (ss >> 6)) * 8192;
                        *(__half*)(base + tile_b_off(dd,     ss & 63)) = __float2half_rn(v0);
                        *(__half*)(base + tile_b_off(dd + 1, ss & 63)) = __float2half_rn(v1);
                    }
                } else {
                    *(float2*)&Cf[(size_t)m * EMB + n] =
                        make_float2(v0 + bias[n], v1 + bias[n + 1]);
                }
            }
        }
}

// ===========================================================================
// fp16 causal flash attention. Q prescaled by 0.125*log2e (base-2 scores),
// exp = bare ex2.approx; l accumulated by a ones-column HMMA (oacc block 8).
// CTA 256 Q rows, 8 warps x 32 rows (MT=2). 2 stages x 16KB + 2 mbarriers.
// ===========================================================================
#define AT_MB     (2 * 16384)
#define ATTN_SMEM (AT_MB + 16)

__global__ __launch_bounds__(256) void attn_tc(const __half* __restrict__ Q,
                                               const __half* __restrict__ Kf,
                                               const __half* __restrict__ Vf,
                                               __half* __restrict__ ctx) {
    extern __shared__ char sma[];
    const uint32_t smb = smem_u32(sma);
    const int tid = threadIdx.x, wid = tid >> 5, lane = tid & 31;
    const int g = lane >> 2, tg = lane & 3;
    const int blkE = gridDim.x - 1 - blockIdx.x;
    const int h = blockIdx.y, b = blockIdx.z;
    const int wrow = blkE * 256 + wid * 32;

    const __half* qb = Q + (((size_t)b * NHEADS + h) * SEQ + wrow) * DHEAD;
    const char* kb = (const char*)Kf + ((size_t)b * NHEADS + h) * 32 * 8192;
    const char* vb = (const char*)Vf + ((size_t)b * NHEADS + h) * 32 * 8192;

    uint32_t qf[2][4][4];
    {
        const float s2e = 0.125f * 1.44269504088896f;   // 1/sqrt(D) * log2(e)
        const __half2 sc = __floats2half2_rn(s2e, s2e);
        const __half2* q2 = (const __half2*)qb;
#pragma unroll
        for (int mt = 0; mt < 2; mt++)
#pragma unroll
            for (int s = 0; s < 4; s++) {
                __half2 h0 = __hmul2(q2[(mt * 16 + g) * 32 + s * 8 + tg], sc);
                __half2 h1 = __hmul2(q2[(mt * 16 + g + 8) * 32 + s * 8 + tg], sc);
                __half2 h2 = __hmul2(q2[(mt * 16 + g) * 32 + s * 8 + tg + 4], sc);
                __half2 h3 = __hmul2(q2[(mt * 16 + g + 8) * 32 + s * 8 + tg + 4], sc);
                qf[mt][s][0] = *(uint32_t*)&h0;
                qf[mt][s][1] = *(uint32_t*)&h1;
                qf[mt][s][2] = *(uint32_t*)&h2;
                qf[mt][s][3] = *(uint32_t*)&h3;
            }
    }

    // oacc blocks 0..7 = O (d columns); block 8 = l (ones column).
    float oacc[2][9][4];
#pragma unroll
    for (int mt = 0; mt < 2; mt++)
#pragma unroll
        for (int nt = 0; nt < 9; nt++)
#pragma unroll
            for (int q = 0; q < 4; q++) oacc[mt][nt][q] = 0.f;
    float m_[2][2] = {{-1e30f, -1e30f}, {-1e30f, -1e30f}};

    if (tid == 0) {
        MBAR_INIT(smb + AT_MB + 0, 1);
        MBAR_INIT(smb + AT_MB + 8, 1);
    }
    __syncthreads();
#define A_ISSUE(jt) do { int _p = (jt) & 1; uint32_t _mb = smb + AT_MB + _p * 8;     \
        MBAR_EXPECT(_mb, 16384u);                                                    \
        bulk_cp(smb + _p * 16384,        kb + (size_t)(jt) * 8192, 8192u, _mb);      \
        bulk_cp(smb + _p * 16384 + 8192, vb + (size_t)(jt) * 8192, 8192u, _mb); } while (0)
    const int nT = 4 * blkE + 4;
    if (tid == 0) A_ISSUE(0);

    const uint32_t ONES = 0x3C003C00u;   // half2(1,1)

    for (int jt = 0; jt < nT; jt++) {
        const int p = jt & 1;
        if (tid == 0 && jt + 1 < nT) A_ISSUE(jt + 1);
        MBAR_WAIT(smb + AT_MB + p * 8, (uint32_t)((jt / 2) & 1));

        if (jt * 64 <= wrow + 31) {
            const char* Ks = sma + p * 16384;
            const char* Vs = Ks + 8192;

            float sacc[2][8][4];
#pragma unroll
            for (int mt = 0; mt < 2; mt++)
#pragma unroll
                for (int nt = 0; nt < 8; nt++)
#pragma unroll
                    for (int q = 0; q < 4; q++) sacc[mt][nt][q] = 0.f;

#pragma unroll
            for (int s = 0; s < 4; s++)
#pragma unroll
                for (int nt = 0; nt < 8; nt++) {
                    uint2 vb2 = *(const uint2*)(Ks + ((nt * 4 + s) * 256) + lane * 8);
                    uint32_t bb2[2] = {vb2.x, vb2.y};
                    mma_f16(sacc[0][nt], qf[0][s], bb2);
                    mma_f16(sacc[1][nt], qf[1][s], bb2);
                }

            if (jt * 64 + 63 > wrow) {
#pragma unroll
                for (int mt = 0; mt < 2; mt++)
#pragma unroll
                    for (int nt = 0; nt < 8; nt++) {
                        int colb = jt * 64 + nt * 8 + 2 * tg;
#pragma unroll
                        for (int rh = 0; rh < 2; rh++) {
                            int row = wrow + mt * 16 + g + 8 * rh;
                            if (colb > row)     sacc[mt][nt][rh * 2 + 0] = -1e30f;
                            if (colb + 1 > row) sacc[mt][nt][rh * 2 + 1] = -1e30f;
                        }
                    }
            }

            // online softmax (base-2): max, alpha, rescale O+l; exp deferred to PV pack
#pragma unroll
            for (int mt = 0; mt < 2; mt++) {
                float rmax[2] = {-1e30f, -1e30f};
#pragma unroll
                for (int nt = 0; nt < 8; nt++)
#pragma unroll
                    for (int rh = 0; rh < 2; rh++)
                        rmax[rh] = fmaxf(rmax[rh],
                                         fmaxf(sacc[mt][nt][rh * 2], sacc[mt][nt][rh * 2 + 1]));
#pragma unroll
                for (int rh = 0; rh < 2; rh++) {
                    rmax[rh] = fmaxf(rmax[rh], __shfl_xor_sync(0xffffffffu, rmax[rh], 1));
                    rmax[rh] = fmaxf(rmax[rh], __shfl_xor_sync(0xffffffffu, rmax[rh], 2));
                }
                float alpha[2];
#pragma unroll
                for (int rh = 0; rh < 2; rh++) {
                    float mnew = fmaxf(m_[mt][rh], rmax[rh]);
                    alpha[rh] = ex2(m_[mt][rh] - mnew);
                    m_[mt][rh] = mnew;
                }
#pragma unroll
                for (int nt = 0; nt < 9; nt++)
#pragma unroll
                    for (int rh = 0; rh < 2; rh++) {
                        oacc[mt][nt][rh * 2 + 0] *= alpha[rh];
                        oacc[mt][nt][rh * 2 + 1] *= alpha[rh];
                    }
            }

            // O += P V, l += P 1  (P = ex2(s - m) packed to fp16 on the fly)
#pragma unroll
            for (int s = 0; s < 4; s++) {
                uint32_t pa[2][4];
#pragma unroll
                for (int mt = 0; mt < 2; mt++) {
                    float m0 = m_[mt][0], m1 = m_[mt][1];
                    pa[mt][0] = pack2(ex2(sacc[mt][2 * s][0] - m0), ex2(sacc[mt][2 * s][1] - m0));
                    pa[mt][1] = pack2(ex2(sacc[mt][2 * s][2] - m1), ex2(sacc[mt][2 * s][3] - m1));
                    pa[mt][2] = pack2(ex2(sacc[mt][2 * s + 1][0] - m0), ex2(sacc[mt][2 * s + 1][1] - m0));
                    pa[mt][3] = pack2(ex2(sacc[mt][2 * s + 1][2] - m1), ex2(sacc[mt][2 * s + 1][3] - m1));
                }
#pragma unroll
                for (int ntd = 0; ntd < 8; ntd++) {
                    uint2 vb2 = *(const uint2*)(Vs + ((ntd * 4 + s) * 256) + lane * 8);
                    uint32_t bb2[2] = {vb2.x, vb2.y};
                    mma_f16(oacc[0][ntd], pa[0], bb2);
                    mma_f16(oacc[1][ntd], pa[1], bb2);
                }
                uint32_t ones2[2] = {ONES, ONES};
                mma_f16(oacc[0][8], pa[0], ones2);
                mma_f16(oacc[1][8], pa[1], ones2);
            }
        }
        __syncthreads();
    }

    // epilogue: O / l -> ctx A-frag file
#pragma unroll
    for (int mt = 0; mt < 2; mt++) {
        float inv[2] = {1.f / oacc[mt][8][0], 1.f / oacc[mt][8][2]};
#pragma unroll
        for (int rh = 0; rh < 2; rh++) {
            const int m = b * SEQ + wrow + mt * 16 + g + 8 * rh;
#pragma unroll
            for (int nt = 0; nt < 8; nt++) {
                int k = h * DHEAD + nt * 8 + 2 * tg;
                *(uint32_t*)((char*)ctx + frag_a_off(m, k, 16)) =
                    pack2(oacc[mt][nt][rh * 2] * inv[rh], oacc[mt][nt][rh * 2 + 1] * inv[rh]);
            }
        }
    }
}

// ---------------------------------------------------------------------------
extern "C" void kernel_launch(void* const* d_in, const int* in_sizes, int n_in,
                              void* d_out, int out_size) {
    const float* x  = (const float*)d_in[0];
    const float* Wk = (const float*)d_in[1];
    const float* Wq = (const float*)d_in[2];
    const float* Wv = (const float*)d_in[3];
    const float* Wu = (const float*)d_in[4];
    const float* bu = (const float*)d_in[5];
    float* out = (float*)d_out;

    __half *qp, *kp, *vp, *cp, *xh, *wk, *wq, *wv, *wu;
    cudaGetSymbolAddress((void**)&qp, g_q);
    cudaGetSymbolAddress((void**)&kp, g_k);
    cudaGetSymbolAddress((void**)&vp, g_v);
    cudaGetSymbolAddress((void**)&cp, g_ctx);
    cudaGetSymbolAddress((void**)&xh, g_xh);
    cudaGetSymbolAddress((void**)&wk, g_wk);
    cudaGetSymbolAddress((void**)&wq, g_wq);
    cudaGetSymbolAddress((void**)&wv, g_wv);
    cudaGetSymbolAddress((void**)&wu, g_wu);

    cudaFuncSetAttribute(gemm_tc<0>, cudaFuncAttributeMaxDynamicSharedMemorySize, GEMM_SMEM);
    cudaFuncSetAttribute(gemm_tc<1>, cudaFuncAttributeMaxDynamicSharedMemorySize, GEMM_SMEM);
    cudaFuncSetAttribute(attn_tc, cudaFuncAttributeMaxDynamicSharedMemorySize, ATTN_SMEM);

    preround<<<8192, 256>>>((const float4*)x, (const float4*)Wk, (const float4*)Wq,
                            (const float4*)Wv, (const float4*)Wu);

    dim3 gqkv(EMB / 128, (NBATCH * SEQ) / 128, 3);
    gemm_tc<0><<<gqkv, 128, GEMM_SMEM>>>((const char*)xh, (const char*)wq, (const char*)wk,
                                         (const char*)wv, qp, kp, vp, nullptr, nullptr);

    attn_tc<<<dim3(SEQ / 256, NHEADS, NBATCH), 256, ATTN_SMEM>>>(qp, kp, vp, cp);

    dim3 go(EMB / 128, (NBATCH * SEQ) / 128, 1);
    gemm_tc<1><<<go, 128, GEMM_SMEM>>>((const char*)cp, (const char*)wu, nullptr, nullptr,
                                       nullptr, nullptr, nullptr, out, bu);
}

// round 16
// speedup vs baseline: 1.0842x; 1.0783x over previous
#include <cuda_runtime.h>
#include <cuda_fp16.h>
#include <cstdint>

#define NHEADS 16
#define SEQ    2048
#define EMB    1024
#define NBATCH 2
#define DHEAD  64

// Fragment-ordered gmem files (device globals; allocation-free rule).
__device__ __half g_xh[NBATCH * SEQ * EMB];    // A-frag file [mb 32][kt 16][16KB]
__device__ __half g_ctx[NBATCH * SEQ * EMB];   // A-frag file (written by attention)
__device__ __half g_wk[EMB * EMB];             // B-frag file [nb 8][kt 16][16KB]
__device__ __half g_wq[EMB * EMB];
__device__ __half g_wv[EMB * EMB];
__device__ __half g_wu[EMB * EMB];
__device__ __half g_q[NBATCH * NHEADS * SEQ * DHEAD];  // [B,H,S,D] linear
__device__ __half g_k[NBATCH * NHEADS * SEQ * DHEAD];  // per (b,h): 32 x 8KB B-frag tiles (n=seq,k=d)
__device__ __half g_v[NBATCH * NHEADS * SEQ * DHEAD];  // per (b,h): 32 x 8KB B-frag tiles (n=d,k=seq)

// ---------------------------------------------------------------------------
__device__ __forceinline__ void mma_f16(float c[4], const uint32_t a[4], const uint32_t b[2]) {
    asm volatile(
        "mma.sync.aligned.m16n8k16.row.col.f32.f16.f16.f32 "
        "{%0,%1,%2,%3}, {%4,%5,%6,%7}, {%8,%9}, {%0,%1,%2,%3};"
        : "+f"(c[0]), "+f"(c[1]), "+f"(c[2]), "+f"(c[3])
        : "r"(a[0]), "r"(a[1]), "r"(a[2]), "r"(a[3]), "r"(b[0]), "r"(b[1]));
}
__device__ __forceinline__ uint32_t pack2(float lo, float hi) {
    __half2 h = __floats2half2_rn(lo, hi);
    return *(uint32_t*)&h;
}
__device__ __forceinline__ float ex2(float x) {
    float y;
    asm("ex2.approx.f32 %0, %1;" : "=f"(y) : "f"(x));
    return y;
}
__device__ __forceinline__ uint32_t smem_u32(const void* p) {
    uint32_t a;
    asm("{ .reg .u64 t; cvta.to.shared.u64 t, %1; cvt.u32.u64 %0, t; }" : "=r"(a) : "l"(p));
    return a;
}
#define MBAR_INIT(addr, cnt) \
    asm volatile("mbarrier.init.shared.b64 [%0], %1;" :: "r"(addr), "r"(cnt) : "memory")
#define MBAR_EXPECT(addr, bytes) \
    asm volatile("mbarrier.arrive.expect_tx.shared.b64 _, [%0], %1;" :: "r"(addr), "r"(bytes) : "memory")
#define MBAR_WAIT(addr, par) do {                                              \
    uint32_t _m = (addr), _p = (par), _d;                                      \
    asm volatile("{ .reg .pred p; mbarrier.try_wait.parity.acquire.cta.shared::cta.b64 p, [%1], %2; selp.b32 %0,1,0,p; }" \
        : "=r"(_d) : "r"(_m), "r"(_p) : "memory");                             \
    while (!_d)                                                                \
        asm volatile("{ .reg .pred p; mbarrier.try_wait.parity.acquire.cta.shared::cta.b64 p, [%1], %2, 0x989680; selp.b32 %0,1,0,p; }" \
            : "=r"(_d) : "r"(_m), "r"(_p) : "memory");                         \
} while (0)
__device__ __forceinline__ void bulk_cp(uint32_t dst, const void* src, uint32_t n, uint32_t mbar) {
    asm volatile(
        "cp.async.bulk.shared::cluster.global.mbarrier::complete_tx::bytes [%0], [%1], %2, [%3];"
        :: "r"(dst), "l"(src), "r"(n), "r"(mbar) : "memory");
}

// Lane-major fragment-file byte offsets.
__device__ __forceinline__ int frag_a_off(int m, int k, int ktiles) {
    int mb = m >> 7, r = m & 127, mt = r >> 4, rr = r & 15;
    int s = (k >> 4) & 3, hf = (k & 15) >> 3, tg = (k & 7) >> 1;
    return (mb * ktiles + (k >> 6)) * 16384 + (mt * 4 + s) * 512 +
           ((rr & 7) * 4 + tg) * 16 + ((rr >> 3) + 2 * hf) * 4 + (k & 1) * 2;
}
__device__ __forceinline__ int frag_b_off(int n, int k, int ktiles) {
    int nb = n >> 7, rn = n & 127;
    int s = (k >> 4) & 3, hf = (k & 15) >> 3, tg = (k & 7) >> 1;
    return (nb * ktiles + (k >> 6)) * 16384 + ((rn >> 3) * 4 + s) * 256 +
           ((rn & 7) * 4 + tg) * 8 + hf * 4 + (k & 1) * 2;
}
__device__ __forceinline__ int tile_b_off(int n, int k) {
    int s = k >> 4, hf = (k & 15) >> 3, tg = (k & 7) >> 1;
    return ((n >> 3) * 4 + s) * 256 + ((n & 7) * 4 + tg) * 8 + hf * 4 + (k & 1) * 2;
}

// ===========================================================================
// Preround: fp32 -> fp16 + permute into fragment files.
// ===========================================================================
__global__ __launch_bounds__(256) void preround(const float4* __restrict__ x,
                                                const float4* __restrict__ wk,
                                                const float4* __restrict__ wq,
                                                const float4* __restrict__ wv,
                                                const float4* __restrict__ wu) {
    int i = blockIdx.x * 256 + threadIdx.x;
    float4 v;
    char* base;
    int o0, o1;
    if (i < 1048576) {
        v = x[i];
        int m = i >> 8, k = (i & 255) * 4;
        base = (char*)g_xh;
        o0 = frag_a_off(m, k, 16);
        o1 = frag_a_off(m, k + 2, 16);
    } else {
        int j = i - 1048576, w = j >> 18, l = j & 262143;
        const float4* src = (w == 0) ? wk : (w == 1) ? wq : (w == 2) ? wv : wu;
        base = (char*)((w == 0) ? g_wk : (w == 1) ? g_wq : (w == 2) ? g_wv : g_wu);
        v = src[l];
        int n = l >> 8, k = (l & 255) * 4;
        o0 = frag_b_off(n, k, 16);
        o1 = frag_b_off(n, k + 2, 16);
    }
    *(uint32_t*)(base + o0) = pack2(v.x, v.y);
    *(uint32_t*)(base + o1) = pack2(v.z, v.w);
}

// ===========================================================================
// fp16 NT GEMM (unchanged from round 13). CTA 128x128, 4 warps (64x64 tiles),
// 16 K-iters, 3 stages x 32KB bulk-copy pipeline.
// ===========================================================================
#define NKT       16
#define STG_B     32768
#define MB_OFF    (3 * STG_B)
#define GEMM_SMEM (MB_OFF + 32)

template <int MODE>
__global__ __launch_bounds__(128) void gemm_tc(const char* __restrict__ Af,
                                               const char* __restrict__ Bw0,
                                               const char* __restrict__ Bw1,
                                               const char* __restrict__ Bw2,
                                               __half* __restrict__ Cq,
                                               __half* __restrict__ Ck,
                                               __half* __restrict__ Cv,
                                               float* __restrict__ Cf,
                                               const float* __restrict__ bias) {
    extern __shared__ char sma[];
    const uint32_t smb = smem_u32(sma);
    const int tid = threadIdx.x, wid = tid >> 5, lane = tid & 31;
    const int z = blockIdx.z;
    const int wm = (wid >> 1) * 64, wn = (wid & 1) * 64;
    const char* Bf = (MODE == 1) ? Bw0 : ((z == 0) ? Bw0 : (z == 1) ? Bw1 : Bw2);
    const char* Ab = Af + (size_t)blockIdx.y * 16 * 16384;
    const char* Bb = Bf + (size_t)blockIdx.x * 16 * 16384;

    if (tid == 0) {
        MBAR_INIT(smb + MB_OFF + 0, 1);
        MBAR_INIT(smb + MB_OFF + 8, 1);
        MBAR_INIT(smb + MB_OFF + 16, 1);
    }
    __syncthreads();
#define G_ISSUE(kt) do { int _st = (kt) % 3; uint32_t _mb = smb + MB_OFF + _st * 8;      \
        MBAR_EXPECT(_mb, 32768u);                                                        \
        bulk_cp(smb + _st * STG_B,         Ab + (size_t)(kt) * 16384, 16384u, _mb);      \
        bulk_cp(smb + _st * STG_B + 16384, Bb + (size_t)(kt) * 16384, 16384u, _mb); } while (0)
    if (tid == 0) { G_ISSUE(0); G_ISSUE(1); }

    float acc[4][8][4];
#pragma unroll
    for (int i = 0; i < 4; i++)
#pragma unroll
        for (int j = 0; j < 8; j++)
#pragma unroll
            for (int q = 0; q < 4; q++) acc[i][j][q] = 0.f;

    const int mtg0 = wm >> 4, ntg0 = wn >> 3;
    for (int kt = 0; kt < NKT; kt++) {
        if (tid == 0 && kt + 2 < NKT) G_ISSUE(kt + 2);
        const int st = kt % 3;
        MBAR_WAIT(smb + MB_OFF + st * 8, (uint32_t)((kt / 3) & 1));

        const char* buf = sma + st * STG_B;
#pragma unroll
        for (int s = 0; s < 4; s++) {
            uint32_t afr[4][4], bfr[8][2];
#pragma unroll
            for (int mt = 0; mt < 4; mt++) {
                uint4 va = *(const uint4*)(buf + ((mtg0 + mt) * 4 + s) * 512 + lane * 16);
                afr[mt][0] = va.x; afr[mt][1] = va.y; afr[mt][2] = va.z; afr[mt][3] = va.w;
            }
#pragma unroll
            for (int nt = 0; nt < 8; nt++) {
                uint2 vb = *(const uint2*)(buf + 16384 + ((ntg0 + nt) * 4 + s) * 256 + lane * 8);
                bfr[nt][0] = vb.x; bfr[nt][1] = vb.y;
            }
#pragma unroll
            for (int mt = 0; mt < 4; mt++)
#pragma unroll
                for (int nt = 0; nt < 8; nt++)
                    mma_f16(acc[mt][nt], afr[mt], bfr[nt]);
        }
        __syncthreads();
    }

    const int g = lane >> 2, tg = lane & 3;
#pragma unroll
    for (int mt = 0; mt < 4; mt++)
#pragma unroll
        for (int rh = 0; rh < 2; rh++) {
            const int m = blockIdx.y * 128 + wm + mt * 16 + g + rh * 8;
#pragma unroll
            for (int nt = 0; nt < 8; nt++) {
                const int n = blockIdx.x * 128 + wn + nt * 8 + tg * 2;
                float v0 = acc[mt][nt][rh * 2], v1 = acc[mt][nt][rh * 2 + 1];
                if (MODE == 0) {
                    const int bb = m >> 11, ss = m & 2047, hh = n >> 6, dd = n & 63;
                    if (z == 0) {
                        *(__half2*)&Cq[(((size_t)bb * NHEADS + hh) * SEQ + ss) * DHEAD + dd] =
                            __floats2half2_rn(v0, v1);
                    } else if (z == 1) {
                        char* base = (char*)Ck + (((size_t)bb * NHEADS + hh) * 32 + (ss >> 6)) * 8192;
                        *(uint32_t*)(base + tile_b_off(ss & 63, dd)) = pack2(v0, v1);
                    } else {
                        char* base = (char*)Cv + (((size_t)bb * NHEADS + hh) * 32 + (ss >> 6)) * 8192;
                        *(__half*)(base + tile_b_off(dd,     ss & 63)) = __float2half_rn(v0);
                        *(__half*)(base + tile_b_off(dd + 1, ss & 63)) = __float2half_rn(v1);
                    }
                } else {
                    *(float2*)&Cf[(size_t)m * EMB + n] =
                        make_float2(v0 + bias[n], v1 + bias[n + 1]);
                }
            }
        }
}

// ===========================================================================
// fp16 causal flash attention — re-grained: CTA = 128 Q rows, 4 warps x 32
// rows (MT=2). 512 CTAs heavy-first -> 1.15 waves, ~3 CTAs/SM resident.
// Base-2 softmax, ones-column l, bulk K/V loads (2 stages x 16KB).
// ===========================================================================
#define AT_MB     (2 * 16384)
#define ATTN_SMEM (AT_MB + 16)

__global__ __launch_bounds__(128) void attn_tc(const __half* __restrict__ Q,
                                               const __half* __restrict__ Kf,
                                               const __half* __restrict__ Vf,
                                               __half* __restrict__ ctx) {
    extern __shared__ char sma[];
    const uint32_t smb = smem_u32(sma);
    const int tid = threadIdx.x, wid = tid >> 5, lane = tid & 31;
    const int g = lane >> 2, tg = lane & 3;
    const int blkE = gridDim.x - 1 - blockIdx.x;   // heavy blocks first
    const int h = blockIdx.y, b = blockIdx.z;
    const int wrow = blkE * 128 + wid * 32;

    const __half* qb = Q + (((size_t)b * NHEADS + h) * SEQ + wrow) * DHEAD;
    const char* kb = (const char*)Kf + ((size_t)b * NHEADS + h) * 32 * 8192;
    const char* vb = (const char*)Vf + ((size_t)b * NHEADS + h) * 32 * 8192;

    uint32_t qf[2][4][4];
    {
        const float s2e = 0.125f * 1.44269504088896f;   // 1/sqrt(D) * log2(e)
        const __half2 sc = __floats2half2_rn(s2e, s2e);
        const __half2* q2 = (const __half2*)qb;
#pragma unroll
        for (int mt = 0; mt < 2; mt++)
#pragma unroll
            for (int s = 0; s < 4; s++) {
                __half2 h0 = __hmul2(q2[(mt * 16 + g) * 32 + s * 8 + tg], sc);
                __half2 h1 = __hmul2(q2[(mt * 16 + g + 8) * 32 + s * 8 + tg], sc);
                __half2 h2 = __hmul2(q2[(mt * 16 + g) * 32 + s * 8 + tg + 4], sc);
                __half2 h3 = __hmul2(q2[(mt * 16 + g + 8) * 32 + s * 8 + tg + 4], sc);
                qf[mt][s][0] = *(uint32_t*)&h0;
                qf[mt][s][1] = *(uint32_t*)&h1;
                qf[mt][s][2] = *(uint32_t*)&h2;
                qf[mt][s][3] = *(uint32_t*)&h3;
            }
    }

    // oacc blocks 0..7 = O; block 8 = l (ones column).
    float oacc[2][9][4];
#pragma unroll
    for (int mt = 0; mt < 2; mt++)
#pragma unroll
        for (int nt = 0; nt < 9; nt++)
#pragma unroll
            for (int q = 0; q < 4; q++) oacc[mt][nt][q] = 0.f;
    float m_[2][2] = {{-1e30f, -1e30f}, {-1e30f, -1e30f}};

    if (tid == 0) {
        MBAR_INIT(smb + AT_MB + 0, 1);
        MBAR_INIT(smb + AT_MB + 8, 1);
    }
    __syncthreads();
#define A_ISSUE(jt) do { int _p = (jt) & 1; uint32_t _mb = smb + AT_MB + _p * 8;     \
        MBAR_EXPECT(_mb, 16384u);                                                    \
        bulk_cp(smb + _p * 16384,        kb + (size_t)(jt) * 8192, 8192u, _mb);      \
        bulk_cp(smb + _p * 16384 + 8192, vb + (size_t)(jt) * 8192, 8192u, _mb); } while (0)
    const int nT = 2 * blkE + 2;
    if (tid == 0) A_ISSUE(0);

    const uint32_t ONES = 0x3C003C00u;

    for (int jt = 0; jt < nT; jt++) {
        const int p = jt & 1;
        if (tid == 0 && jt + 1 < nT) A_ISSUE(jt + 1);
        MBAR_WAIT(smb + AT_MB + p * 8, (uint32_t)((jt / 2) & 1));

        if (jt * 64 <= wrow + 31) {
            const char* Ks = sma + p * 16384;
            const char* Vs = Ks + 8192;

            float sacc[2][8][4];
#pragma unroll
            for (int mt = 0; mt < 2; mt++)
#pragma unroll
                for (int nt = 0; nt < 8; nt++)
#pragma unroll
                    for (int q = 0; q < 4; q++) sacc[mt][nt][q] = 0.f;

#pragma unroll
            for (int s = 0; s < 4; s++)
#pragma unroll
                for (int nt = 0; nt < 8; nt++) {
                    uint2 vb2 = *(const uint2*)(Ks + ((nt * 4 + s) * 256) + lane * 8);
                    uint32_t bb2[2] = {vb2.x, vb2.y};
                    mma_f16(sacc[0][nt], qf[0][s], bb2);
                    mma_f16(sacc[1][nt], qf[1][s], bb2);
                }

            if (jt * 64 + 63 > wrow) {
#pragma unroll
                for (int mt = 0; mt < 2; mt++)
#pragma unroll
                    for (int nt = 0; nt < 8; nt++) {
                        int colb = jt * 64 + nt * 8 + 2 * tg;
#pragma unroll
                        for (int rh = 0; rh < 2; rh++) {
                            int row = wrow + mt * 16 + g + 8 * rh;
                            if (colb > row)     sacc[mt][nt][rh * 2 + 0] = -1e30f;
                            if (colb + 1 > row) sacc[mt][nt][rh * 2 + 1] = -1e30f;
                        }
                    }
            }

#pragma unroll
            for (int mt = 0; mt < 2; mt++) {
                float rmax[2] = {-1e30f, -1e30f};
#pragma unroll
                for (int nt = 0; nt < 8; nt++)
#pragma unroll
                    for (int rh = 0; rh < 2; rh++)
                        rmax[rh] = fmaxf(rmax[rh],
                                         fmaxf(sacc[mt][nt][rh * 2], sacc[mt][nt][rh * 2 + 1]));
#pragma unroll
                for (int rh = 0; rh < 2; rh++) {
                    rmax[rh] = fmaxf(rmax[rh], __shfl_xor_sync(0xffffffffu, rmax[rh], 1));
                    rmax[rh] = fmaxf(rmax[rh], __shfl_xor_sync(0xffffffffu, rmax[rh], 2));
                }
                float alpha[2];
#pragma unroll
                for (int rh = 0; rh < 2; rh++) {
                    float mnew = fmaxf(m_[mt][rh], rmax[rh]);
                    alpha[rh] = ex2(m_[mt][rh] - mnew);
                    m_[mt][rh] = mnew;
                }
#pragma unroll
                for (int nt = 0; nt < 9; nt++)
#pragma unroll
                    for (int rh = 0; rh < 2; rh++) {
                        oacc[mt][nt][rh * 2 + 0] *= alpha[rh];
                        oacc[mt][nt][rh * 2 + 1] *= alpha[rh];
                    }
            }

#pragma unroll
            for (int s = 0; s < 4; s++) {
                uint32_t pa[2][4];
#pragma unroll
                for (int mt = 0; mt < 2; mt++) {
                    float m0 = m_[mt][0], m1 = m_[mt][1];
                    pa[mt][0] = pack2(ex2(sacc[mt][2 * s][0] - m0), ex2(sacc[mt][2 * s][1] - m0));
                    pa[mt][1] = pack2(ex2(sacc[mt][2 * s][2] - m1), ex2(sacc[mt][2 * s][3] - m1));
                    pa[mt][2] = pack2(ex2(sacc[mt][2 * s + 1][0] - m0), ex2(sacc[mt][2 * s + 1][1] - m0));
                    pa[mt][3] = pack2(ex2(sacc[mt][2 * s + 1][2] - m1), ex2(sacc[mt][2 * s + 1][3] - m1));
                }
#pragma unroll
                for (int ntd = 0; ntd < 8; ntd++) {
                    uint2 vb2 = *(const uint2*)(Vs + ((ntd * 4 + s) * 256) + lane * 8);
                    uint32_t bb2[2] = {vb2.x, vb2.y};
                    mma_f16(oacc[0][ntd], pa[0], bb2);
                    mma_f16(oacc[1][ntd], pa[1], bb2);
                }
                uint32_t ones2[2] = {ONES, ONES};
                mma_f16(oacc[0][8], pa[0], ones2);
                mma_f16(oacc[1][8], pa[1], ones2);
            }
        }
        __syncthreads();
    }

    // epilogue: O / l -> ctx A-frag file
#pragma unroll
    for (int mt = 0; mt < 2; mt++) {
        float inv[2] = {1.f / oacc[mt][8][0], 1.f / oacc[mt][8][2]};
#pragma unroll
        for (int rh = 0; rh < 2; rh++) {
            const int m = b * SEQ + wrow + mt * 16 + g + 8 * rh;
#pragma unroll
            for (int nt = 0; nt < 8; nt++) {
                int k = h * DHEAD + nt * 8 + 2 * tg;
                *(uint32_t*)((char*)ctx + frag_a_off(m, k, 16)) =
                    pack2(oacc[mt][nt][rh * 2] * inv[rh], oacc[mt][nt][rh * 2 + 1] * inv[rh]);
            }
        }
    }
}

// ---------------------------------------------------------------------------
extern "C" void kernel_launch(void* const* d_in, const int* in_sizes, int n_in,
                              void* d_out, int out_size) {
    const float* x  = (const float*)d_in[0];
    const float* Wk = (const float*)d_in[1];
    const float* Wq = (const float*)d_in[2];
    const float* Wv = (const float*)d_in[3];
    const float* Wu = (const float*)d_in[4];
    const float* bu = (const float*)d_in[5];
    float* out = (float*)d_out;

    __half *qp, *kp, *vp, *cp, *xh, *wk, *wq, *wv, *wu;
    cudaGetSymbolAddress((void**)&qp, g_q);
    cudaGetSymbolAddress((void**)&kp, g_k);
    cudaGetSymbolAddress((void**)&vp, g_v);
    cudaGetSymbolAddress((void**)&cp, g_ctx);
    cudaGetSymbolAddress((void**)&xh, g_xh);
    cudaGetSymbolAddress((void**)&wk, g_wk);
    cudaGetSymbolAddress((void**)&wq, g_wq);
    cudaGetSymbolAddress((void**)&wv, g_wv);
    cudaGetSymbolAddress((void**)&wu, g_wu);

    cudaFuncSetAttribute(gemm_tc<0>, cudaFuncAttributeMaxDynamicSharedMemorySize, GEMM_SMEM);
    cudaFuncSetAttribute(gemm_tc<1>, cudaFuncAttributeMaxDynamicSharedMemorySize, GEMM_SMEM);
    cudaFuncSetAttribute(attn_tc, cudaFuncAttributeMaxDynamicSharedMemorySize, ATTN_SMEM);

    preround<<<8192, 256>>>((const float4*)x, (const float4*)Wk, (const float4*)Wq,
                            (const float4*)Wv, (const float4*)Wu);

    dim3 gqkv(EMB / 128, (NBATCH * SEQ) / 128, 3);
    gemm_tc<0><<<gqkv, 128, GEMM_SMEM>>>((const char*)xh, (const char*)wq, (const char*)wk,
                                         (const char*)wv, qp, kp, vp, nullptr, nullptr);

    attn_tc<<<dim3(SEQ / 128, NHEADS, NBATCH), 128, ATTN_SMEM>>>(qp, kp, vp, cp);

    dim3 go(EMB / 128, (NBATCH * SEQ) / 128, 1);
    gemm_tc<1><<<go, 128, GEMM_SMEM>>>((const char*)cp, (const char*)wu, nullptr, nullptr,
                                       nullptr, nullptr, nullptr, out, bu);
}